// round 6
// baseline (speedup 1.0000x reference)
#include <cuda_runtime.h>
#include <cstdint>

#define BB 32
#define NN 512
#define HH 128
constexpr float LN_EPS = 1e-5f;

// h transposed AND pre-converted to tf32 bits: g_hT[b][d][j]  (B, H, N), 8 MB
__device__ uint32_t g_hT[(size_t)BB * HH * NN];

// ---------------------------------------------------------------------------
// helpers
// ---------------------------------------------------------------------------
__device__ __forceinline__ uint32_t f2tf32(float x) {
    uint32_t r;
    asm("cvt.rna.tf32.f32 %0, %1;" : "=r"(r) : "f"(x));
    return r;
}

__device__ __forceinline__ uint32_t smem_u32(const void* p) {
    uint32_t a;
    asm("{ .reg .u64 t; cvta.to.shared.u64 t, %1; cvt.u32.u64 %0, t; }"
        : "=r"(a) : "l"(p));
    return a;
}

__device__ __forceinline__ void mma_sync_tf32(float* d, const uint32_t* a, const uint32_t* b) {
    asm volatile(
        "mma.sync.aligned.m16n8k8.row.col.f32.tf32.tf32.f32 "
        "{%0,%1,%2,%3}, {%4,%5,%6,%7}, {%8,%9}, {%0,%1,%2,%3};\n"
        : "+f"(d[0]), "+f"(d[1]), "+f"(d[2]), "+f"(d[3])
        : "r"(a[0]), "r"(a[1]), "r"(a[2]), "r"(a[3]), "r"(b[0]), "r"(b[1]));
}

__device__ __forceinline__ void ldm4(uint32_t* r, uint32_t saddr) {
    asm volatile(
        "ldmatrix.sync.aligned.m8n8.x4.shared.b16 {%0,%1,%2,%3}, [%4];"
        : "=r"(r[0]), "=r"(r[1]), "=r"(r[2]), "=r"(r[3])
        : "r"(saddr));
}

__device__ __forceinline__ void cp16(uint32_t dst, const void* src) {
    asm volatile("cp.async.cg.shared.global [%0], [%1], 16;"
                 :: "r"(dst), "l"(src) : "memory");
}
__device__ __forceinline__ void cp_commit() {
    asm volatile("cp.async.commit_group;" ::: "memory");
}
template<int N> __device__ __forceinline__ void cp_wait() {
    asm volatile("cp.async.wait_group %0;" :: "n"(N) : "memory");
}

// ---------------------------------------------------------------------------
// Stage 1: h = silu(layernorm(s @ W1^T + b1)), stored TRANSPOSED + tf32 bits
// ---------------------------------------------------------------------------
__global__ __launch_bounds__(256) void lin1_ln_silu_kernel(
    const float* __restrict__ s, const float* __restrict__ W1,
    const float* __restrict__ b1)
{
    __shared__ float smem[64 * 133];
    float* As = smem;                 // [64][36]
    float* Bs = smem + 64 * 36;       // [128][36]
    float* Hs = smem;                 // [64][133]

    const int tid  = threadIdx.x;
    const int r0   = blockIdx.x * 64;
    const int w    = tid >> 5;
    const int lane = tid & 31;
    const int g    = lane >> 2;
    const int tg   = lane & 3;
    const int wm   = w & 1;
    const int wn   = w >> 1;

    float acc[2][4][4];
    #pragma unroll
    for (int i = 0; i < 2; i++)
        #pragma unroll
        for (int j = 0; j < 4; j++)
            #pragma unroll
            for (int k = 0; k < 4; k++) acc[i][j][k] = 0.f;

    const uint32_t* A32 = (const uint32_t*)As;
    const uint32_t* B32 = (const uint32_t*)Bs;

    for (int kc = 0; kc < 4; kc++) {
        const int k0 = kc * 32;
        __syncthreads();
        #pragma unroll
        for (int it = 0; it < 2; it++) {
            int idx = tid + it * 256;
            int row = idx >> 3, q = idx & 7;
            float4 v = *(const float4*)(s + (size_t)(r0 + row) * HH + k0 + q * 4);
            uint32_t* dst = (uint32_t*)(As + row * 36 + q * 4);
            dst[0] = f2tf32(v.x); dst[1] = f2tf32(v.y);
            dst[2] = f2tf32(v.z); dst[3] = f2tf32(v.w);
        }
        #pragma unroll
        for (int it = 0; it < 4; it++) {
            int idx = tid + it * 256;
            int n = idx >> 3, q = idx & 7;
            float4 v = *(const float4*)(W1 + (size_t)n * HH + k0 + q * 4);
            uint32_t* dst = (uint32_t*)(Bs + n * 36 + q * 4);
            dst[0] = f2tf32(v.x); dst[1] = f2tf32(v.y);
            dst[2] = f2tf32(v.z); dst[3] = f2tf32(v.w);
        }
        __syncthreads();
        #pragma unroll
        for (int ks = 0; ks < 4; ks++) {
            const int kk = ks * 8;
            uint32_t af[2][4], bf[4][2];
            #pragma unroll
            for (int mt = 0; mt < 2; mt++) {
                int rm = wm * 32 + mt * 16;
                af[mt][0] = A32[(rm + g) * 36 + kk + tg];
                af[mt][1] = A32[(rm + g + 8) * 36 + kk + tg];
                af[mt][2] = A32[(rm + g) * 36 + kk + tg + 4];
                af[mt][3] = A32[(rm + g + 8) * 36 + kk + tg + 4];
            }
            #pragma unroll
            for (int nt = 0; nt < 4; nt++) {
                int cn = wn * 32 + nt * 8 + g;
                bf[nt][0] = B32[cn * 36 + kk + tg];
                bf[nt][1] = B32[cn * 36 + kk + tg + 4];
            }
            #pragma unroll
            for (int mt = 0; mt < 2; mt++)
                #pragma unroll
                for (int nt = 0; nt < 4; nt++)
                    mma_sync_tf32(acc[mt][nt], af[mt], bf[nt]);
        }
    }

    __syncthreads();
    #pragma unroll
    for (int mt = 0; mt < 2; mt++) {
        #pragma unroll
        for (int nt = 0; nt < 4; nt++) {
            int rm = wm * 32 + mt * 16 + g;
            int cn = wn * 32 + nt * 8 + 2 * tg;
            Hs[rm * 133 + cn]           = acc[mt][nt][0];
            Hs[rm * 133 + cn + 1]       = acc[mt][nt][1];
            Hs[(rm + 8) * 133 + cn]     = acc[mt][nt][2];
            Hs[(rm + 8) * 133 + cn + 1] = acc[mt][nt][3];
        }
    }
    __syncthreads();

    #pragma unroll
    for (int rr = 0; rr < 8; rr++) {
        int row = w * 8 + rr;
        float x[4];
        float sum = 0.f, sq = 0.f;
        #pragma unroll
        for (int k = 0; k < 4; k++) {
            float v = Hs[row * 133 + lane + 32 * k] + __ldg(b1 + lane + 32 * k);
            x[k] = v; sum += v; sq += v * v;
        }
        #pragma unroll
        for (int o = 16; o > 0; o >>= 1) {
            sum += __shfl_xor_sync(0xffffffffu, sum, o);
            sq  += __shfl_xor_sync(0xffffffffu, sq, o);
        }
        float mu  = sum * (1.f / 128.f);
        float var = sq * (1.f / 128.f) - mu * mu;
        float inv = rsqrtf(var + LN_EPS);
        #pragma unroll
        for (int k = 0; k < 4; k++) {
            float yv = (x[k] - mu) * inv;
            Hs[row * 133 + lane + 32 * k] = yv / (1.f + __expf(-yv));
        }
    }
    __syncthreads();

    // Transposed write-out as tf32 bits: g_hT[b][d][n]
    const int b  = r0 >> 9;
    const int n0 = r0 & 511;
    #pragma unroll
    for (int it = 0; it < 8; it++) {
        int idx = tid + it * 256;
        int d = idx >> 4;
        int q = idx & 15;
        uint4 v;
        v.x = f2tf32(Hs[(q * 4 + 0) * 133 + d]);
        v.y = f2tf32(Hs[(q * 4 + 1) * 133 + d]);
        v.z = f2tf32(Hs[(q * 4 + 2) * 133 + d]);
        v.w = f2tf32(Hs[(q * 4 + 3) * 133 + d]);
        *(uint4*)(g_hT + ((size_t)b * HH + d) * NN + n0 + q * 4) = v;
    }
}

// ---------------------------------------------------------------------------
// Stage 2: mma.sync tf32 GEMM. K-chunk 64 (8 chunks), ev reg-staged across
// the MMA block, B + mask via cp.async ring depth 3.
// Block: batch b, m-tile 128 (m=i*3+c), N=128 (d), K=512 (j).
// 512 threads = 16 warps (4x4), warp tile 32m x 32n.
// ---------------------------------------------------------------------------
#define AST64 68
#define OFF_A0 0u
#define OFF_A1 34816u
#define OFF_B  69632u       /* + r*32768 */
#define OFF_MK 167936u      /* + r*11264 */
#define SMEM2  201728

__global__ __launch_bounds__(512, 1)
void cfconv4_kernel(const float* __restrict__ ev,
                    const float* __restrict__ mask,
                    float* __restrict__ out)
{
    extern __shared__ __align__(16) char smemc[];
    const uint32_t sb = smem_u32(smemc);

    const int tid  = threadIdx.x;
    const int w    = tid >> 5;
    const int lane = tid & 31;
    const int g    = lane >> 2;
    const int tg   = lane & 3;
    const int wm   = w & 3;       // 4 warp rows (32 m each)
    const int wn   = w >> 2;      // 4 warp cols (32 n each)

    const int b    = blockIdx.y;
    const int m0   = blockIdx.x * 128;
    const int i_lo = m0 / 3;
    const int i_hi = (m0 + 127) / 3;
    const int icnt = i_hi - i_lo + 1;     // <= 44

    const float*    evB   = ev   + (((size_t)b * NN) * NN) * 3;
    const float*    maskB = mask + ((size_t)b * NN) * NN;
    const uint32_t* hTB   = g_hT + ((size_t)b * HH) * NN;

    // ldmatrix per-lane constants (verified mappings)
    const int arow  = (lane & 7) + ((lane >> 3) & 1) * 8;
    const int ahalf = (lane >> 4) & 1;
    const uint32_t aoff = (uint32_t)(((wm * 32 + arow) * AST64 + ahalf * 4) * 4);
    const int brow  = (lane & 7) + ((lane >> 4) & 1) * 8;
    const int bhalf = (lane >> 3) & 1;

    float acc[2][4][4];
    #pragma unroll
    for (int mt = 0; mt < 2; mt++)
        #pragma unroll
        for (int nt = 0; nt < 4; nt++)
            #pragma unroll
            for (int k = 0; k < 4; k++) acc[mt][nt][k] = 0.f;

    // per-thread ev staging decomposition (row = 48 float4 of 192 floats)
    int erow[5], eq[5];
    #pragma unroll
    for (int it = 0; it < 5; it++) {
        int idx = tid + it * 512;
        erow[it] = idx / 48;
        eq[it]   = idx - erow[it] * 48;
    }
    const int ev_n = icnt * 48;

    // ---- cp.async: B (h_T) + mask for chunk ch ----
    auto issue = [&](int ch) {
        const int r  = ch % 3;
        const int j0 = ch * 64;
        const uint32_t bb = sb + OFF_B + (uint32_t)r * 32768u;
        #pragma unroll
        for (int it = 0; it < 4; it++) {
            int idx = tid + it * 512;
            int d = idx >> 4, q = idx & 15;
            cp16(bb + (uint32_t)(d * 256 + ((q ^ (d & 7)) << 4)),
                 hTB + (size_t)d * NN + j0 + q * 4);
        }
        const uint32_t mb = sb + OFF_MK + (uint32_t)r * 11264u;
        #pragma unroll
        for (int it = 0; it < 2; it++) {
            int idx = tid + it * 512;
            if (idx < icnt * 16) {
                cp16(mb + (uint32_t)idx * 16u,
                     maskB + (size_t)(i_lo + (idx >> 4)) * NN + j0 + (idx & 15) * 4);
            }
        }
        cp_commit();
    };

    // ---- stage ev for chunk ch into registers ----
    float4 evr[5];
    auto stage_ev = [&](int ch) {
        const int j0 = ch * 64;
        #pragma unroll
        for (int it = 0; it < 5; it++) {
            int idx = tid + it * 512;
            if (idx < ev_n)
                evr[it] = *(const float4*)(evB +
                    ((size_t)(i_lo + erow[it]) * NN + j0) * 3 + eq[it] * 4);
        }
    };

    // ---- scatter staged ev * mask -> A[p], mask from ring slot of chunk ch ----
    auto scatterA = [&](int p, int ch) {
        const int r = ch % 3;
        const float* mkr = (const float*)(smemc + OFF_MK + (size_t)r * 11264u);
        uint32_t* Ab = (uint32_t*)(smemc + (p ? OFF_A1 : OFF_A0));
        #pragma unroll
        for (int it = 0; it < 5; it++) {
            int idx = tid + it * 512;
            if (idx < ev_n) {
                int rr = erow[it], q = eq[it];
                int jc0 = q * 4, ja = jc0 / 3;
                float mA = mkr[rr * 64 + ja];
                float mB2 = mkr[rr * 64 + ja + 1];
                int mbase = (i_lo + rr) * 3 - m0;
                float fv[4] = {evr[it].x, evr[it].y, evr[it].z, evr[it].w};
                #pragma unroll
                for (int e = 0; e < 4; e++) {
                    int jc = jc0 + e;
                    int jl = jc / 3, c = jc - 3 * jl;
                    int m = mbase + c;
                    if (m >= 0 && m < 128)
                        Ab[m * AST64 + jl] = f2tf32(fv[e] * (jl == ja ? mA : mB2));
                }
            }
        }
    };

    // Prologue: 3 chunks of B/mask in flight; build A0.
    issue(0); issue(1); issue(2);
    cp_wait<2>();
    __syncthreads();
    stage_ev(0);
    scatterA(0, 0);
    __syncthreads();

    for (int ch = 0; ch < 8; ch++) {
        const int p = ch & 1;
        const uint32_t Ab = sb + (p ? OFF_A1 : OFF_A0);
        const uint32_t Bb = sb + OFF_B + (uint32_t)(ch % 3) * 32768u;

        // Hoisted LDG for next chunk's ev — latency overlaps the MMA block.
        if (ch < 7) stage_ev(ch + 1);

        // MMA: 8 k-steps of 8
        #pragma unroll
        for (int ks = 0; ks < 8; ks++) {
            uint32_t af[2][4], bf[2][4];
            #pragma unroll
            for (int mt = 0; mt < 2; mt++)
                ldm4(af[mt], Ab + aoff + (uint32_t)(mt * 16 * AST64 * 4 + ks * 32));
            #pragma unroll
            for (int bt = 0; bt < 2; bt++) {
                int n = wn * 32 + bt * 16 + brow;
                int jq = ks * 2 + bhalf;
                ldm4(bf[bt], Bb + (uint32_t)(n * 256 + ((jq ^ (n & 7)) << 4)));
            }
            #pragma unroll
            for (int mt = 0; mt < 2; mt++)
                #pragma unroll
                for (int nt = 0; nt < 4; nt++)
                    mma_sync_tf32(acc[mt][nt], af[mt], &bf[nt >> 1][(nt & 1) * 2]);
        }

        if (ch < 6)       cp_wait<1>();
        else if (ch == 6) cp_wait<0>();
        __syncthreads();

        if (ch < 7) {
            scatterA(p ^ 1, ch + 1);
            if (ch < 5) issue(ch + 3);
        }
        __syncthreads();
    }

    // Epilogue
    const size_t obase = ((size_t)b * 1536 + m0) * HH;
    #pragma unroll
    for (int mt = 0; mt < 2; mt++) {
        #pragma unroll
        for (int nt = 0; nt < 4; nt++) {
            int m  = wm * 32 + mt * 16 + g;
            int cn = wn * 32 + nt * 8 + 2 * tg;
            *(float2*)(out + obase + (size_t)m * HH + cn) =
                make_float2(acc[mt][nt][0], acc[mt][nt][1]);
            *(float2*)(out + obase + (size_t)(m + 8) * HH + cn) =
                make_float2(acc[mt][nt][2], acc[mt][nt][3]);
        }
    }
}

// ---------------------------------------------------------------------------
// Launch
// ---------------------------------------------------------------------------
extern "C" void kernel_launch(void* const* d_in, const int* in_sizes, int n_in,
                              void* d_out, int out_size) {
    (void)in_sizes; (void)n_in; (void)out_size;
    const float* s    = (const float*)d_in[0];
    const float* ev   = (const float*)d_in[1];
    const float* mask = (const float*)d_in[2];
    const float* W1   = (const float*)d_in[3];
    const float* b1   = (const float*)d_in[4];
    float* out = (float*)d_out;

    cudaFuncSetAttribute(cfconv4_kernel,
                         cudaFuncAttributeMaxDynamicSharedMemorySize, SMEM2);

    lin1_ln_silu_kernel<<<256, 256>>>(s, W1, b1);
    cfconv4_kernel<<<dim3(12, 32), 512, SMEM2>>>(ev, mask, out);
}